// round 12
// baseline (speedup 1.0000x reference)
#include <cuda_runtime.h>
#include <cuda_bf16.h>

#define NPTS 1048576
#define KNEI 16
#define NTASKS (2 * NPTS)          // 2 tasks per point, 8 nbrs each
#define GRID_MAIN 888              // 148 SMs x 6 CTAs (reg cap via launch_bounds)
#define NTHREADS 256

// Padded points: 16B rows -> each random gather = exactly one L1tex
// wavefront / one 32B L2 sector. This is the irreducible cost driver:
// 16.8M divergent gathers = 16.8M wavefronts, and the main kernel runs at
// that L1tex floor (~72.5us). All measured deviations regress (see journal).
__device__ float4 g_pts4[NPTS];
__device__ double g_acc;
__device__ unsigned int g_ticket;

// Kernel 1: pad [N,3] f32 -> [N] float4 (4 points per thread) and reset
// accumulator + ticket (every graph replay). PDL trigger fires once this
// block's stores are issued so the main kernel can ramp up under our tail.
__global__ void __launch_bounds__(256) pad_points_kernel(const float* __restrict__ pts) {
    int i = blockIdx.x * blockDim.x + threadIdx.x;   // 0 .. 262143
    if (i == 0) { g_acc = 0.0; g_ticket = 0u; }

    const float4* p4 = reinterpret_cast<const float4*>(pts) + 3 * i;
    float4 a = p4[0];
    float4 b = p4[1];
    float4 c = p4[2];

    int o = 4 * i;
    g_pts4[o + 0] = make_float4(a.x, a.y, a.z, 0.0f);
    g_pts4[o + 1] = make_float4(a.w, b.x, b.y, 0.0f);
    g_pts4[o + 2] = make_float4(b.z, b.w, c.x, 0.0f);
    g_pts4[o + 3] = make_float4(c.y, c.z, c.w, 0.0f);

    cudaTriggerProgrammaticLaunchCompletion();
}

// Kernel 2: persistent grid-stride over 2M pair-tasks (8 neighbours each).
// Proven 40-reg barrier-free loop; PDL sync at the top only. Plain loads
// throughout (every cache-hint / staging / batching variant measured slower).
__global__ void __launch_bounds__(NTHREADS, 6) neighbour_loss_kernel(
    const int* __restrict__ idx,
    const float* __restrict__ orig,
    float* __restrict__ out)
{
    // Wait for pad kernel's results (PDL overlap happens before this point).
    cudaGridDependencySynchronize();

    const int stride = GRID_MAIN * NTHREADS;
    float tsum = 0.0f;

    for (int t = blockIdx.x * NTHREADS + threadIdx.x; t < NTASKS; t += stride) {
        int n = t >> 1;   // point id

        const int4* idx4 = reinterpret_cast<const int4*>(idx) + t * 2;
        int4 i0 = idx4[0];
        int4 i1 = idx4[1];

        // 8 independent 16B gathers — all outstanding simultaneously.
        float4 q0 = __ldg(&g_pts4[i0.x]);
        float4 q1 = __ldg(&g_pts4[i0.y]);
        float4 q2 = __ldg(&g_pts4[i0.z]);
        float4 q3 = __ldg(&g_pts4[i0.w]);
        float4 q4 = __ldg(&g_pts4[i1.x]);
        float4 q5 = __ldg(&g_pts4[i1.y]);
        float4 q6 = __ldg(&g_pts4[i1.z]);
        float4 q7 = __ldg(&g_pts4[i1.w]);

        const float4* orig4 = reinterpret_cast<const float4*>(orig) + t * 2;
        float4 o0 = orig4[0];
        float4 o1 = orig4[1];
        float4 p  = g_pts4[n];

        float dx, dy, dz, curr, e;
        #define ACC(q, ov)                                        \
            dx = p.x - q.x; dy = p.y - q.y; dz = p.z - q.z;       \
            curr = fmaf(dx, dx, fmaf(dy, dy, dz * dz));           \
            e = curr - ov;                                        \
            tsum = fmaf(e, e, tsum);
        ACC(q0, o0.x) ACC(q1, o0.y) ACC(q2, o0.z) ACC(q3, o0.w)
        ACC(q4, o1.x) ACC(q5, o1.y) ACC(q6, o1.z) ACC(q7, o1.w)
        #undef ACC
    }

    // ---- reduce: warp -> block -> global; fused finalize ----
    #pragma unroll
    for (int off = 16; off > 0; off >>= 1)
        tsum += __shfl_down_sync(0xFFFFFFFFu, tsum, off);

    __shared__ float warp_sums[8];
    int lane = threadIdx.x & 31;
    int wid  = threadIdx.x >> 5;
    if (lane == 0) warp_sums[wid] = tsum;
    __syncthreads();
    if (wid == 0) {
        float bs = (lane < 8) ? warp_sums[lane] : 0.0f;
        #pragma unroll
        for (int off = 4; off > 0; off >>= 1)
            bs += __shfl_down_sync(0xFFFFFFFFu, bs, off);
        if (lane == 0) {
            atomicAdd(&g_acc, (double)bs);
            __threadfence();
            unsigned tk = atomicAdd(&g_ticket, 1u);
            if (tk == GRID_MAIN - 1) {
                double total = atomicAdd(&g_acc, 0.0);   // atomic read
                out[0] = (float)(total * (100000.0 / 16777216.0));
            }
        }
    }
}

extern "C" void kernel_launch(void* const* d_in, const int* in_sizes, int n_in,
                              void* d_out, int out_size) {
    const float* points = (const float*)d_in[0];
    const int*   nidx   = (const int*)d_in[1];
    const float* orig   = (const float*)d_in[2];
    float* out = (float*)d_out;

    (void)in_sizes; (void)n_in; (void)out_size;

    pad_points_kernel<<<1024, 256>>>(points);   // 4 pts/thread

    // Main kernel with Programmatic Dependent Launch: its launch/ramp
    // overlaps the pad kernel's tail; cudaGridDependencySynchronize()
    // inside the kernel enforces correctness.
    cudaLaunchConfig_t cfg = {};
    cfg.gridDim  = dim3(GRID_MAIN);
    cfg.blockDim = dim3(NTHREADS);
    cfg.dynamicSmemBytes = 0;
    cfg.stream = 0;
    cudaLaunchAttribute attrs[1];
    attrs[0].id = cudaLaunchAttributeProgrammaticStreamSerialization;
    attrs[0].val.programmaticStreamSerializationAllowed = 1;
    cfg.attrs = attrs;
    cfg.numAttrs = 1;
    cudaLaunchKernelEx(&cfg, neighbour_loss_kernel, nidx, orig, out);
}

// round 13
// speedup vs baseline: 1.0267x; 1.0267x over previous
#include <cuda_runtime.h>
#include <cuda_bf16.h>

#define NPTS 1048576
#define KNEI 16
#define NTASKS (2 * NPTS)          // 2 tasks per point, 8 nbrs each
#define GRID_MAIN 912              // GB300 has 152 SMs (not 148!) x 6 CTAs
#define NTHREADS 256

// Padded points: 16B rows -> each random gather = exactly one L1tex
// wavefront / one 32B L2 sector. This is the irreducible cost driver:
// 16.8M divergent gathers = 16.8M wavefronts; the main kernel runs at that
// per-SM L1tex floor. All measured loop deviations regress (see journal).
__device__ float4 g_pts4[NPTS];
__device__ double g_acc;
__device__ unsigned int g_ticket;

// Kernel 1: pad [N,3] f32 -> [N] float4 (4 points per thread) and reset
// accumulator + ticket (every graph replay). PDL trigger fires once this
// block's stores are issued so the main kernel can ramp up under our tail.
__global__ void __launch_bounds__(256) pad_points_kernel(const float* __restrict__ pts) {
    int i = blockIdx.x * blockDim.x + threadIdx.x;   // 0 .. 262143
    if (i == 0) { g_acc = 0.0; g_ticket = 0u; }

    const float4* p4 = reinterpret_cast<const float4*>(pts) + 3 * i;
    float4 a = p4[0];
    float4 b = p4[1];
    float4 c = p4[2];

    int o = 4 * i;
    g_pts4[o + 0] = make_float4(a.x, a.y, a.z, 0.0f);
    g_pts4[o + 1] = make_float4(a.w, b.x, b.y, 0.0f);
    g_pts4[o + 2] = make_float4(b.z, b.w, c.x, 0.0f);
    g_pts4[o + 3] = make_float4(c.y, c.z, c.w, 0.0f);

    cudaTriggerProgrammaticLaunchCompletion();
}

// Kernel 2: persistent grid-stride over 2M pair-tasks (8 neighbours each).
// Proven 40-reg barrier-free loop; PDL sync at the top only. Plain loads
// throughout (every cache-hint / staging / batching variant measured slower).
// Grid = 152 SMs x 6 CTAs so every SM carries identical wavefront load.
__global__ void __launch_bounds__(NTHREADS, 6) neighbour_loss_kernel(
    const int* __restrict__ idx,
    const float* __restrict__ orig,
    float* __restrict__ out)
{
    // Wait for pad kernel's results (PDL overlap happens before this point).
    cudaGridDependencySynchronize();

    const int stride = GRID_MAIN * NTHREADS;
    float tsum = 0.0f;

    for (int t = blockIdx.x * NTHREADS + threadIdx.x; t < NTASKS; t += stride) {
        int n = t >> 1;   // point id

        const int4* idx4 = reinterpret_cast<const int4*>(idx) + t * 2;
        int4 i0 = idx4[0];
        int4 i1 = idx4[1];

        // 8 independent 16B gathers — all outstanding simultaneously.
        float4 q0 = __ldg(&g_pts4[i0.x]);
        float4 q1 = __ldg(&g_pts4[i0.y]);
        float4 q2 = __ldg(&g_pts4[i0.z]);
        float4 q3 = __ldg(&g_pts4[i0.w]);
        float4 q4 = __ldg(&g_pts4[i1.x]);
        float4 q5 = __ldg(&g_pts4[i1.y]);
        float4 q6 = __ldg(&g_pts4[i1.z]);
        float4 q7 = __ldg(&g_pts4[i1.w]);

        const float4* orig4 = reinterpret_cast<const float4*>(orig) + t * 2;
        float4 o0 = orig4[0];
        float4 o1 = orig4[1];
        float4 p  = g_pts4[n];

        float dx, dy, dz, curr, e;
        #define ACC(q, ov)                                        \
            dx = p.x - q.x; dy = p.y - q.y; dz = p.z - q.z;       \
            curr = fmaf(dx, dx, fmaf(dy, dy, dz * dz));           \
            e = curr - ov;                                        \
            tsum = fmaf(e, e, tsum);
        ACC(q0, o0.x) ACC(q1, o0.y) ACC(q2, o0.z) ACC(q3, o0.w)
        ACC(q4, o1.x) ACC(q5, o1.y) ACC(q6, o1.z) ACC(q7, o1.w)
        #undef ACC
    }

    // ---- reduce: warp -> block -> global; fused finalize ----
    #pragma unroll
    for (int off = 16; off > 0; off >>= 1)
        tsum += __shfl_down_sync(0xFFFFFFFFu, tsum, off);

    __shared__ float warp_sums[8];
    int lane = threadIdx.x & 31;
    int wid  = threadIdx.x >> 5;
    if (lane == 0) warp_sums[wid] = tsum;
    __syncthreads();
    if (wid == 0) {
        float bs = (lane < 8) ? warp_sums[lane] : 0.0f;
        #pragma unroll
        for (int off = 4; off > 0; off >>= 1)
            bs += __shfl_down_sync(0xFFFFFFFFu, bs, off);
        if (lane == 0) {
            atomicAdd(&g_acc, (double)bs);
            __threadfence();
            unsigned tk = atomicAdd(&g_ticket, 1u);
            if (tk == GRID_MAIN - 1) {
                double total = atomicAdd(&g_acc, 0.0);   // atomic read
                out[0] = (float)(total * (100000.0 / 16777216.0));
            }
        }
    }
}

extern "C" void kernel_launch(void* const* d_in, const int* in_sizes, int n_in,
                              void* d_out, int out_size) {
    const float* points = (const float*)d_in[0];
    const int*   nidx   = (const int*)d_in[1];
    const float* orig   = (const float*)d_in[2];
    float* out = (float*)d_out;

    (void)in_sizes; (void)n_in; (void)out_size;

    pad_points_kernel<<<1024, 256>>>(points);   // 4 pts/thread

    // Main kernel with Programmatic Dependent Launch: its launch/ramp
    // overlaps the pad kernel's tail; cudaGridDependencySynchronize()
    // inside the kernel enforces correctness.
    cudaLaunchConfig_t cfg = {};
    cfg.gridDim  = dim3(GRID_MAIN);
    cfg.blockDim = dim3(NTHREADS);
    cfg.dynamicSmemBytes = 0;
    cfg.stream = 0;
    cudaLaunchAttribute attrs[1];
    attrs[0].id = cudaLaunchAttributeProgrammaticStreamSerialization;
    attrs[0].val.programmaticStreamSerializationAllowed = 1;
    cfg.attrs = attrs;
    cfg.numAttrs = 1;
    cudaLaunchKernelEx(&cfg, neighbour_loss_kernel, nidx, orig, out);
}

// round 14
// speedup vs baseline: 1.0456x; 1.0184x over previous
#include <cuda_runtime.h>
#include <cuda_bf16.h>

#define NPTS 1048576
#define KNEI 16
#define NTASKS (2 * NPTS)          // 2 tasks per point, 8 nbrs each
#define GRID_MAIN 912              // GB300: 152 SMs x 6 CTAs (balanced)
#define NTHREADS 256

// Padded points: 16B rows -> each random gather = exactly one L1tex
// wavefront / one 32B L2 sector. This is the irreducible cost driver:
// 16.8M divergent gathers = 16.8M wavefronts; the main kernel runs at that
// per-SM L1tex floor (~69.7us at grid 912). All loop deviations regress.
__device__ float4 g_pts4[NPTS];
__device__ double g_acc;
__device__ unsigned int g_ticket;

// Kernel 1: pad [N,3] f32 -> [N] float4 (4 points per thread) and reset
// accumulator + ticket (every graph replay). PDL trigger fires once this
// block's stores are issued so the main kernel can ramp up under our tail.
__global__ void __launch_bounds__(256) pad_points_kernel(const float* __restrict__ pts) {
    int i = blockIdx.x * blockDim.x + threadIdx.x;   // 0 .. 262143
    if (i == 0) { g_acc = 0.0; g_ticket = 0u; }

    const float4* p4 = reinterpret_cast<const float4*>(pts) + 3 * i;
    float4 a = p4[0];
    float4 b = p4[1];
    float4 c = p4[2];

    int o = 4 * i;
    g_pts4[o + 0] = make_float4(a.x, a.y, a.z, 0.0f);
    g_pts4[o + 1] = make_float4(a.w, b.x, b.y, 0.0f);
    g_pts4[o + 2] = make_float4(b.z, b.w, c.x, 0.0f);
    g_pts4[o + 3] = make_float4(c.y, c.z, c.w, 0.0f);

    cudaTriggerProgrammaticLaunchCompletion();
}

// Kernel 2: persistent grid-stride over 2M pair-tasks (8 neighbours each).
// Proven 40-reg barrier-free loop; PDL sync at the top only. Plain loads;
// all loads of an iteration issued up-front for maximum in-flight depth.
__global__ void __launch_bounds__(NTHREADS, 6) neighbour_loss_kernel(
    const int* __restrict__ idx,
    const float* __restrict__ orig,
    float* __restrict__ out)
{
    // Wait for pad kernel's results (PDL overlap happens before this point).
    cudaGridDependencySynchronize();

    const int stride = GRID_MAIN * NTHREADS;
    float tsum = 0.0f;

    for (int t = blockIdx.x * NTHREADS + threadIdx.x; t < NTASKS; t += stride) {
        int n = t >> 1;   // point id

        const int4* idx4 = reinterpret_cast<const int4*>(idx) + t * 2;
        int4 i0 = idx4[0];
        int4 i1 = idx4[1];

        // Streamed loads issued together with the gathers (one LDG burst).
        const float4* orig4 = reinterpret_cast<const float4*>(orig) + t * 2;
        float4 o0 = orig4[0];
        float4 o1 = orig4[1];
        float4 p  = g_pts4[n];

        // 8 independent 16B gathers — all outstanding simultaneously.
        float4 q0 = __ldg(&g_pts4[i0.x]);
        float4 q1 = __ldg(&g_pts4[i0.y]);
        float4 q2 = __ldg(&g_pts4[i0.z]);
        float4 q3 = __ldg(&g_pts4[i0.w]);
        float4 q4 = __ldg(&g_pts4[i1.x]);
        float4 q5 = __ldg(&g_pts4[i1.y]);
        float4 q6 = __ldg(&g_pts4[i1.z]);
        float4 q7 = __ldg(&g_pts4[i1.w]);

        float dx, dy, dz, curr, e;
        #define ACC(q, ov)                                        \
            dx = p.x - q.x; dy = p.y - q.y; dz = p.z - q.z;       \
            curr = fmaf(dx, dx, fmaf(dy, dy, dz * dz));           \
            e = curr - ov;                                        \
            tsum = fmaf(e, e, tsum);
        ACC(q0, o0.x) ACC(q1, o0.y) ACC(q2, o0.z) ACC(q3, o0.w)
        ACC(q4, o1.x) ACC(q5, o1.y) ACC(q6, o1.z) ACC(q7, o1.w)
        #undef ACC
    }

    // ---- reduce: warp -> block -> global; fused finalize ----
    #pragma unroll
    for (int off = 16; off > 0; off >>= 1)
        tsum += __shfl_down_sync(0xFFFFFFFFu, tsum, off);

    __shared__ float warp_sums[8];
    int lane = threadIdx.x & 31;
    int wid  = threadIdx.x >> 5;
    if (lane == 0) warp_sums[wid] = tsum;
    __syncthreads();
    if (wid == 0) {
        float bs = (lane < 8) ? warp_sums[lane] : 0.0f;
        #pragma unroll
        for (int off = 4; off > 0; off >>= 1)
            bs += __shfl_down_sync(0xFFFFFFFFu, bs, off);
        if (lane == 0) {
            atomicAdd(&g_acc, (double)bs);
            __threadfence();
            unsigned tk = atomicAdd(&g_ticket, 1u);
            if (tk == GRID_MAIN - 1) {
                double total = atomicAdd(&g_acc, 0.0);   // atomic read
                out[0] = (float)(total * (100000.0 / 16777216.0));
            }
        }
    }
}

extern "C" void kernel_launch(void* const* d_in, const int* in_sizes, int n_in,
                              void* d_out, int out_size) {
    const float* points = (const float*)d_in[0];
    const int*   nidx   = (const int*)d_in[1];
    const float* orig   = (const float*)d_in[2];
    float* out = (float*)d_out;

    (void)in_sizes; (void)n_in; (void)out_size;

    pad_points_kernel<<<1024, 256>>>(points);   // 4 pts/thread

    // Main kernel with Programmatic Dependent Launch: its launch/ramp
    // overlaps the pad kernel's tail; cudaGridDependencySynchronize()
    // inside the kernel enforces correctness.
    cudaLaunchConfig_t cfg = {};
    cfg.gridDim  = dim3(GRID_MAIN);
    cfg.blockDim = dim3(NTHREADS);
    cfg.dynamicSmemBytes = 0;
    cfg.stream = 0;
    cudaLaunchAttribute attrs[1];
    attrs[0].id = cudaLaunchAttributeProgrammaticStreamSerialization;
    attrs[0].val.programmaticStreamSerializationAllowed = 1;
    cfg.attrs = attrs;
    cfg.numAttrs = 1;
    cudaLaunchKernelEx(&cfg, neighbour_loss_kernel, nidx, orig, out);
}

// round 15
// speedup vs baseline: 1.0638x; 1.0174x over previous
#include <cuda_runtime.h>
#include <cuda_bf16.h>

#define NPTS 1048576
#define KNEI 16
#define NTASKS (2 * NPTS)          // 2 tasks per point, 8 nbrs each
#define GRID_MAIN 912              // GB300: 152 SMs x 6 CTAs (balanced)
#define NTHREADS 256

// Padded points: 16B rows -> each random gather = exactly one L1tex
// wavefront / one 32B L2 sector. 16.8M divergent gathers = 16.8M wavefronts;
// the main kernel runs at that per-SM L1tex floor. Gathers use .cg (L2-only,
// no L1 allocation) since the 16MB table gives ~1.5% L1 hit rate — the
// allocation/evict churn is pure overhead in the binding L1tex pipeline.
__device__ float4 g_pts4[NPTS];
__device__ double g_acc;
__device__ unsigned int g_ticket;

// Kernel 1: pad [N,3] f32 -> [N] float4 (4 points per thread) and reset
// accumulator + ticket (every graph replay). PDL trigger fires once this
// block's stores are issued so the main kernel can ramp up under our tail.
__global__ void __launch_bounds__(256) pad_points_kernel(const float* __restrict__ pts) {
    int i = blockIdx.x * blockDim.x + threadIdx.x;   // 0 .. 262143
    if (i == 0) { g_acc = 0.0; g_ticket = 0u; }

    const float4* p4 = reinterpret_cast<const float4*>(pts) + 3 * i;
    float4 a = p4[0];
    float4 b = p4[1];
    float4 c = p4[2];

    int o = 4 * i;
    g_pts4[o + 0] = make_float4(a.x, a.y, a.z, 0.0f);
    g_pts4[o + 1] = make_float4(a.w, b.x, b.y, 0.0f);
    g_pts4[o + 2] = make_float4(b.z, b.w, c.x, 0.0f);
    g_pts4[o + 3] = make_float4(c.y, c.z, c.w, 0.0f);

    cudaTriggerProgrammaticLaunchCompletion();
}

// Kernel 2: persistent grid-stride over 2M pair-tasks (8 neighbours each).
// Proven 40-reg barrier-free loop; PDL sync at the top only; all loads of
// an iteration issued up-front. Streams/p keep default caching (they hit L1).
__global__ void __launch_bounds__(NTHREADS, 6) neighbour_loss_kernel(
    const int* __restrict__ idx,
    const float* __restrict__ orig,
    float* __restrict__ out)
{
    // Wait for pad kernel's results (PDL overlap happens before this point).
    cudaGridDependencySynchronize();

    const int stride = GRID_MAIN * NTHREADS;
    float tsum = 0.0f;

    for (int t = blockIdx.x * NTHREADS + threadIdx.x; t < NTASKS; t += stride) {
        int n = t >> 1;   // point id

        const int4* idx4 = reinterpret_cast<const int4*>(idx) + t * 2;
        int4 i0 = idx4[0];
        int4 i1 = idx4[1];

        // Streamed loads issued together with the gathers (one LDG burst).
        const float4* orig4 = reinterpret_cast<const float4*>(orig) + t * 2;
        float4 o0 = orig4[0];
        float4 o1 = orig4[1];
        float4 p  = g_pts4[n];

        // 8 independent 16B gathers — L2-direct (.cg), no L1 allocation.
        float4 q0 = __ldcg(&g_pts4[i0.x]);
        float4 q1 = __ldcg(&g_pts4[i0.y]);
        float4 q2 = __ldcg(&g_pts4[i0.z]);
        float4 q3 = __ldcg(&g_pts4[i0.w]);
        float4 q4 = __ldcg(&g_pts4[i1.x]);
        float4 q5 = __ldcg(&g_pts4[i1.y]);
        float4 q6 = __ldcg(&g_pts4[i1.z]);
        float4 q7 = __ldcg(&g_pts4[i1.w]);

        float dx, dy, dz, curr, e;
        #define ACC(q, ov)                                        \
            dx = p.x - q.x; dy = p.y - q.y; dz = p.z - q.z;       \
            curr = fmaf(dx, dx, fmaf(dy, dy, dz * dz));           \
            e = curr - ov;                                        \
            tsum = fmaf(e, e, tsum);
        ACC(q0, o0.x) ACC(q1, o0.y) ACC(q2, o0.z) ACC(q3, o0.w)
        ACC(q4, o1.x) ACC(q5, o1.y) ACC(q6, o1.z) ACC(q7, o1.w)
        #undef ACC
    }

    // ---- reduce: warp -> block -> global; fused finalize ----
    #pragma unroll
    for (int off = 16; off > 0; off >>= 1)
        tsum += __shfl_down_sync(0xFFFFFFFFu, tsum, off);

    __shared__ float warp_sums[8];
    int lane = threadIdx.x & 31;
    int wid  = threadIdx.x >> 5;
    if (lane == 0) warp_sums[wid] = tsum;
    __syncthreads();
    if (wid == 0) {
        float bs = (lane < 8) ? warp_sums[lane] : 0.0f;
        #pragma unroll
        for (int off = 4; off > 0; off >>= 1)
            bs += __shfl_down_sync(0xFFFFFFFFu, bs, off);
        if (lane == 0) {
            atomicAdd(&g_acc, (double)bs);
            __threadfence();
            unsigned tk = atomicAdd(&g_ticket, 1u);
            if (tk == GRID_MAIN - 1) {
                double total = atomicAdd(&g_acc, 0.0);   // atomic read
                out[0] = (float)(total * (100000.0 / 16777216.0));
            }
        }
    }
}

extern "C" void kernel_launch(void* const* d_in, const int* in_sizes, int n_in,
                              void* d_out, int out_size) {
    const float* points = (const float*)d_in[0];
    const int*   nidx   = (const int*)d_in[1];
    const float* orig   = (const float*)d_in[2];
    float* out = (float*)d_out;

    (void)in_sizes; (void)n_in; (void)out_size;

    pad_points_kernel<<<1024, 256>>>(points);   // 4 pts/thread

    // Main kernel with Programmatic Dependent Launch: its launch/ramp
    // overlaps the pad kernel's tail; cudaGridDependencySynchronize()
    // inside the kernel enforces correctness.
    cudaLaunchConfig_t cfg = {};
    cfg.gridDim  = dim3(GRID_MAIN);
    cfg.blockDim = dim3(NTHREADS);
    cfg.dynamicSmemBytes = 0;
    cfg.stream = 0;
    cudaLaunchAttribute attrs[1];
    attrs[0].id = cudaLaunchAttributeProgrammaticStreamSerialization;
    attrs[0].val.programmaticStreamSerializationAllowed = 1;
    cfg.attrs = attrs;
    cfg.numAttrs = 1;
    cudaLaunchKernelEx(&cfg, neighbour_loss_kernel, nidx, orig, out);
}